// round 16
// baseline (speedup 1.0000x reference)
#include <cuda_runtime.h>
#include <math.h>

#define BATCH 64
#define NTOT  65536
#define DIM   1024
#define NPIECE 296        // exactly one wave: 2 CTAs x 148 SMs
#define NSPLIT 16

// ---------------- device scratch (static, no allocation) ----------------
__device__ float  g_vpart[NSPLIT * BATCH * DIM];
__device__ float  g_v[BATCH * DIM];
__device__ int    g_chunk_seg[NPIECE];
__device__ int    g_chunk_start[NPIECE];
__device__ int    g_chunk_cnt[NPIECE];
__device__ int    g_seg_chunk_start[BATCH];
__device__ int    g_seg_chunk_cnt[BATCH];
__device__ float  g_part_m[NPIECE];
__device__ float  g_part_z[NPIECE];
__device__ float4 g_part_acc[NPIECE * (DIM / 4)];
__device__ int    g_tile_done[NSPLIT];   // split-K arrivals; self-cleaning
__device__ int    g_seg_done[BATCH];     // per-segment piece arrivals; self-cleaning

// packed f32x2 helpers (sm_103a FFMA2 — PTX-only)
#define FMA2(d, a, b, c) \
    asm("fma.rn.f32x2 %0, %1, %2, %3;" : "=l"(d) : "l"(a), "l"(b), "l"(c))
#define PACK2(out, lo, hi) \
    asm("mov.b64 %0, {%1, %2};" : "=l"(out) : "f"(lo), "f"(hi))

// ============ K1: v-projection (f32x2) + split-K reduce + balanced setup ============
__global__ void k1_vproj_setup(const float* __restrict__ dstate,
                               const float* __restrict__ W,
                               const int* __restrict__ lens_raw) {
    __shared__ unsigned long long dsh2[8][64];   // 16 b's packed into 8 f32x2, 64 h
    int m  = blockIdx.x * 256 + threadIdx.x;
    int b0 = blockIdx.y * 16;
    int h0 = blockIdx.z * 64;

    for (int i = threadIdx.x; i < 8 * 64; i += 256) {
        int p = i >> 6, hh = i & 63;
        float lo = dstate[(b0 + 2 * p)     * DIM + h0 + hh];
        float hi = dstate[(b0 + 2 * p + 1) * DIM + h0 + hh];
        unsigned long long pk; PACK2(pk, lo, hi);
        dsh2[p][hh] = pk;
    }
    __syncthreads();

    unsigned long long acc2[8];
#pragma unroll
    for (int i = 0; i < 8; i++) acc2[i] = 0ull;

#pragma unroll 4
    for (int hh = 0; hh < 64; hh++) {
        float w = W[(size_t)(h0 + hh) * DIM + m];
        unsigned long long w2; PACK2(w2, w, w);
#pragma unroll
        for (int i = 0; i < 8; i++) FMA2(acc2[i], dsh2[i][hh], w2, acc2[i]);
    }

    float* outp = g_vpart + (size_t)blockIdx.z * (BATCH * DIM);
#pragma unroll
    for (int i = 0; i < 8; i++) {
        unsigned long long a = acc2[i];
        outp[(b0 + 2 * i)     * DIM + m] = __int_as_float((int)(a & 0xffffffffull));
        outp[(b0 + 2 * i + 1) * DIM + m] = __int_as_float((int)(a >> 32));
    }

    // ---- last z-split for this (bx,by) tile reduces the 16 partials ----
    __shared__ int s_last;
    __threadfence();
    __syncthreads();
    if (threadIdx.x == 0)
        s_last = (atomicAdd(&g_tile_done[blockIdx.y * 4 + blockIdx.x], 1) == NSPLIT - 1) ? 1 : 0;
    __syncthreads();
    if (s_last) {
        __threadfence();   // acquire: make all splits' writes visible
        for (int i = threadIdx.x; i < 16 * 256; i += 256) {
            int bl = i >> 8, mm = i & 255;
            int b  = blockIdx.y * 16 + bl;
            int mc = blockIdx.x * 256 + mm;
            float s = 0.f;
#pragma unroll
            for (int p = 0; p < NSPLIT; p++)
                s += g_vpart[(size_t)p * BATCH * DIM + b * DIM + mc];
            g_v[b * DIM + mc] = s;
        }
        if (threadIdx.x == 0)
            g_tile_done[blockIdx.y * 4 + blockIdx.x] = 0;   // self-clean for replay
    }

    // ---- balanced ragged partition in block (0,0,0) ----
    if (blockIdx.x == 0 && blockIdx.y == 0 && blockIdx.z == 0) {
        __shared__ int s_len[BATCH], s_nck[BATCH], s_noff[BATCH], s_coff[BATCH];
        __shared__ int s_red[64];
        __shared__ int s_tp;
        int b = threadIdx.x;
        const long long* lens64 = (const long long*)lens_raw;
        bool is64 = (lens_raw[1] == 0);   // int64 LE: high word of elem0 is 0
        int mylen = 0;
        if (b < BATCH) {
            mylen = is64 ? (int)lens64[b] : lens_raw[b];
            s_len[b] = mylen;
            // floor allocation: sum <= NPIECE guaranteed
            long long x = (long long)mylen * NPIECE / NTOT;
            int nck = (int)x; if (nck < 1) nck = 1;
            s_nck[b] = nck;
        }
        __syncthreads();
        if (b == 0) {
            int tp = 0;
            for (int i = 0; i < BATCH; i++) tp += s_nck[i];
            s_tp = tp;
        }
        __syncthreads();
        // distribute leftover slots to the segment with the largest piece
        while (s_tp < NPIECE) {
            int piece = (b < BATCH) ? (s_len[b] + s_nck[b] - 1) / s_nck[b] : 0;
            int packed = (piece << 6) | b;        // argmax, deterministic tiebreak
            s_red[b < 64 ? b : 0] = (b < 64) ? packed : 0;
            __syncthreads();
#pragma unroll
            for (int off = 32; off > 0; off >>= 1) {
                if (b < off) {
                    int o = s_red[b + off];
                    if (o > s_red[b]) s_red[b] = o;
                }
                __syncthreads();
            }
            if (b == 0) {
                s_nck[s_red[0] & 63]++;
                s_tp++;
            }
            __syncthreads();
        }
        // prefix sums + piece table
        if (b == 0) {
            int noff = 0, coff = 0;
            for (int i = 0; i < BATCH; i++) {
                s_noff[i] = noff; s_coff[i] = coff;
                noff += s_len[i];
                coff += s_nck[i];
            }
        }
        __syncthreads();
        if (b < BATCH) {
            int len = s_len[b], nck = s_nck[b];
            int cs  = s_coff[b];
            g_seg_chunk_start[b] = cs;
            g_seg_chunk_cnt[b]   = nck;
            int base = len / nck, rem = len % nck;   // first rem pieces get +1
            int off = s_noff[b];
            for (int k = 0; k < nck; k++) {
                int cnt = base + (k < rem ? 1 : 0);
                g_chunk_seg[cs + k]   = b;
                g_chunk_start[cs + k] = off;
                g_chunk_cnt[cs + k]   = cnt;
                off += cnt;
            }
        }
    }
}

// ============ K2: one CTA = one balanced piece (R4 loop) + last-arriver combine ============
__global__ void __launch_bounds__(256, 2) k2_phase1(const float* __restrict__ mem,
                                                    float* __restrict__ out) {
    __shared__ float4 s_acc[8][256];   // 32 KB per-warp accumulators
    __shared__ float  s_m[8], s_z[8];
    __shared__ int    s_last;

    int c     = blockIdx.x;
    int cnt   = g_chunk_cnt[c];
    int seg   = g_chunk_seg[c];
    int start = g_chunk_start[c];
    int warp  = threadIdx.x >> 5;
    int lane  = threadIdx.x & 31;
    int t     = threadIdx.x;

    // v row for this segment (L2-hot), register-resident (R4-proven layout)
    const float4* vp = (const float4*)(g_v + seg * DIM);
    float4 v[8];
#pragma unroll
    for (int j = 0; j < 8; j++) v[j] = vp[j * 32 + lane];

    float m = -INFINITY, z = 0.f;
    float4 acc[8];
#pragma unroll
    for (int j = 0; j < 8; j++) acc[j] = make_float4(0.f, 0.f, 0.f, 0.f);

    for (int i = warp; i < cnt; i += 8) {
        const float4* row = (const float4*)(mem + (size_t)(start + i) * DIM);
        float4 r[8];
#pragma unroll
        for (int j = 0; j < 8; j++) r[j] = row[j * 32 + lane];

        float s = 0.f;
#pragma unroll
        for (int j = 0; j < 8; j++)
            s += r[j].x * v[j].x + r[j].y * v[j].y + r[j].z * v[j].z + r[j].w * v[j].w;
#pragma unroll
        for (int o = 16; o > 0; o >>= 1) s += __shfl_xor_sync(0xffffffffu, s, o);

        if (s > m) {
            float sc = __expf(m - s);   // exp(-inf)=0 handles first row
            z = z * sc + 1.f;
#pragma unroll
            for (int j = 0; j < 8; j++) {
                acc[j].x = acc[j].x * sc + r[j].x;
                acc[j].y = acc[j].y * sc + r[j].y;
                acc[j].z = acc[j].z * sc + r[j].z;
                acc[j].w = acc[j].w * sc + r[j].w;
            }
            m = s;
        } else {
            float w8 = __expf(s - m);
            z += w8;
#pragma unroll
            for (int j = 0; j < 8; j++) {
                acc[j].x = fmaf(w8, r[j].x, acc[j].x);
                acc[j].y = fmaf(w8, r[j].y, acc[j].y);
                acc[j].z = fmaf(w8, r[j].z, acc[j].z);
                acc[j].w = fmaf(w8, r[j].w, acc[j].w);
            }
        }
    }

    // combine 8 warp-local accumulators -> piece partial
#pragma unroll
    for (int j = 0; j < 8; j++) s_acc[warp][j * 32 + lane] = acc[j];
    if (lane == 0) { s_m[warp] = m; s_z[warp] = z; }
    __syncthreads();

    float m_b = -INFINITY;
#pragma unroll
    for (int w = 0; w < 8; w++) m_b = fmaxf(m_b, s_m[w]);

    float  z_b = 0.f;
    float4 a   = make_float4(0.f, 0.f, 0.f, 0.f);
#pragma unroll
    for (int w = 0; w < 8; w++) {
        float mw = s_m[w];
        float sc = (mw == -INFINITY) ? 0.f : __expf(mw - m_b);  // idle warp -> 0
        float4 aw = s_acc[w][t];
        a.x = fmaf(sc, aw.x, a.x);
        a.y = fmaf(sc, aw.y, a.y);
        a.z = fmaf(sc, aw.z, a.z);
        a.w = fmaf(sc, aw.w, a.w);
        z_b = fmaf(sc, s_z[w], z_b);
    }
    g_part_acc[c * (DIM / 4) + t] = a;
    if (t == 0) { g_part_m[c] = m_b; g_part_z[c] = z_b; }

    // ---- event-driven last-arriver: final combine for this segment ----
    __threadfence();
    __syncthreads();
    if (t == 0)
        s_last = (atomicAdd(&g_seg_done[seg], 1) == g_seg_chunk_cnt[seg] - 1) ? 1 : 0;
    __syncthreads();
    if (s_last) {
        __threadfence();   // acquire: other pieces' partials now visible
        int cs = g_seg_chunk_start[seg];
        int cc = g_seg_chunk_cnt[seg];

        float m_g = -INFINITY;
        for (int ci = 0; ci < cc; ci++) m_g = fmaxf(m_g, g_part_m[cs + ci]);

        float  zg = 0.f;
        float4 ag = make_float4(0.f, 0.f, 0.f, 0.f);
        for (int ci = 0; ci < cc; ci++) {
            float sc = __expf(g_part_m[cs + ci] - m_g);
            float4 p = g_part_acc[(cs + ci) * (DIM / 4) + t];
            ag.x = fmaf(sc, p.x, ag.x);
            ag.y = fmaf(sc, p.y, ag.y);
            ag.z = fmaf(sc, p.z, ag.z);
            ag.w = fmaf(sc, p.w, ag.w);
            zg = fmaf(sc, g_part_z[cs + ci], zg);
        }
        float inv = 1.f / zg;
        ((float4*)out)[seg * (DIM / 4) + t] =
            make_float4(ag.x * inv, ag.y * inv, ag.z * inv, ag.w * inv);
        if (t == 0) g_seg_done[seg] = 0;   // self-clean for graph replay
    }
}

// ---------------- launch ----------------
extern "C" void kernel_launch(void* const* d_in, const int* in_sizes, int n_in,
                              void* d_out, int out_size) {
    // Identify inputs by element count (ordering-proof):
    //   memory_bank 67108864, decoder_state 65536, W 1048576, lens 64.
    const float* mem    = nullptr;
    const float* dstate = nullptr;
    const float* W      = nullptr;
    const int*   lens   = nullptr;
    for (int i = 0; i < n_in; i++) {
        switch (in_sizes[i]) {
            case 67108864: mem    = (const float*)d_in[i]; break;
            case 65536:    dstate = (const float*)d_in[i]; break;
            case 1048576:  W      = (const float*)d_in[i]; break;
            case 64:       lens   = (const int*)d_in[i];   break;
        }
    }
    float* out = (float*)d_out;

    k1_vproj_setup<<<dim3(4, 4, NSPLIT), 256>>>(dstate, W, lens);
    k2_phase1<<<NPIECE, 256>>>(mem, out);
}

// round 17
// speedup vs baseline: 1.1046x; 1.1046x over previous
#include <cuda_runtime.h>
#include <math.h>

#define BATCH 64
#define NTOT  65536
#define DIM   1024
#define NPIECE 296        // one wave: 2 CTAs x 148 SMs
#define SLAB  222         // ceil(NTOT/NPIECE); last slab = 46 rows
#define SLOTS 16          // max slabs per segment (max len ~1548 -> <=8 +1)
#define NSPLIT 16
#define RING_BYTES (8 * 2 * 4096)   // 8 warps x 2 bufs x 4KB = 64KB dynamic smem

// ---------------- device scratch (static, no allocation) ----------------
__device__ float  g_vpart[NSPLIT * BATCH * DIM];
__device__ float  g_v[BATCH * DIM];
__device__ int    g_seg_node_start[BATCH + 1];
__device__ float  g_part_m[BATCH * SLOTS];
__device__ float  g_part_z[BATCH * SLOTS];
__device__ float4 g_part_acc[BATCH * SLOTS * (DIM / 4)];
__device__ int    g_tile_done[NSPLIT];   // split-K arrivals; self-cleaning
__device__ int    g_seg_done[BATCH];     // per-segment piece arrivals; self-cleaning

// packed f32x2 helpers (sm_103a FFMA2 — PTX-only)
#define FMA2(d, a, b, c) \
    asm("fma.rn.f32x2 %0, %1, %2, %3;" : "=l"(d) : "l"(a), "l"(b), "l"(c))
#define PACK2(out, lo, hi) \
    asm("mov.b64 %0, {%1, %2};" : "=l"(out) : "f"(lo), "f"(hi))

// cp.async helpers
#define CP_ASYNC16(dst_u32, src_ptr) \
    asm volatile("cp.async.cg.shared.global [%0], [%1], 16;" :: "r"(dst_u32), "l"(src_ptr))
#define CP_COMMIT() asm volatile("cp.async.commit_group;")
#define CP_WAIT1()  asm volatile("cp.async.wait_group 1;")
#define CP_WAIT0()  asm volatile("cp.async.wait_group 0;")

// ============ K1: v-projection (f32x2) + split-K reduce + prefix setup ============
__global__ void k1_vproj_setup(const float* __restrict__ dstate,
                               const float* __restrict__ W,
                               const int* __restrict__ lens_raw) {
    __shared__ unsigned long long dsh2[8][64];
    int m  = blockIdx.x * 256 + threadIdx.x;
    int b0 = blockIdx.y * 16;
    int h0 = blockIdx.z * 64;

    for (int i = threadIdx.x; i < 8 * 64; i += 256) {
        int p = i >> 6, hh = i & 63;
        float lo = dstate[(b0 + 2 * p)     * DIM + h0 + hh];
        float hi = dstate[(b0 + 2 * p + 1) * DIM + h0 + hh];
        unsigned long long pk; PACK2(pk, lo, hi);
        dsh2[p][hh] = pk;
    }
    __syncthreads();

    unsigned long long acc2[8];
#pragma unroll
    for (int i = 0; i < 8; i++) acc2[i] = 0ull;

#pragma unroll 4
    for (int hh = 0; hh < 64; hh++) {
        float w = W[(size_t)(h0 + hh) * DIM + m];
        unsigned long long w2; PACK2(w2, w, w);
#pragma unroll
        for (int i = 0; i < 8; i++) FMA2(acc2[i], dsh2[i][hh], w2, acc2[i]);
    }

    float* outp = g_vpart + (size_t)blockIdx.z * (BATCH * DIM);
#pragma unroll
    for (int i = 0; i < 8; i++) {
        unsigned long long a = acc2[i];
        outp[(b0 + 2 * i)     * DIM + m] = __int_as_float((int)(a & 0xffffffffull));
        outp[(b0 + 2 * i + 1) * DIM + m] = __int_as_float((int)(a >> 32));
    }

    __shared__ int s_last;
    __threadfence();
    __syncthreads();
    if (threadIdx.x == 0)
        s_last = (atomicAdd(&g_tile_done[blockIdx.y * 4 + blockIdx.x], 1) == NSPLIT - 1) ? 1 : 0;
    __syncthreads();
    if (s_last) {
        __threadfence();
        for (int i = threadIdx.x; i < 16 * 256; i += 256) {
            int bl = i >> 8, mm = i & 255;
            int b  = blockIdx.y * 16 + bl;
            int mc = blockIdx.x * 256 + mm;
            float s = 0.f;
#pragma unroll
            for (int p = 0; p < NSPLIT; p++)
                s += g_vpart[(size_t)p * BATCH * DIM + b * DIM + mc];
            g_v[b * DIM + mc] = s;
        }
        if (threadIdx.x == 0)
            g_tile_done[blockIdx.y * 4 + blockIdx.x] = 0;   // self-clean
    }

    // ---- trivial prefix setup (block (0,0,0)) ----
    if (blockIdx.x == 0 && blockIdx.y == 0 && blockIdx.z == 0) {
        __shared__ int s_len[BATCH];
        int b = threadIdx.x;
        const long long* lens64 = (const long long*)lens_raw;
        bool is64 = (lens_raw[1] == 0);   // int64 LE: high word of elem0 is 0
        if (b < BATCH) s_len[b] = is64 ? (int)lens64[b] : lens_raw[b];
        __syncthreads();
        if (b == 0) {
            int off = 0;
            for (int i = 0; i < BATCH; i++) { g_seg_node_start[i] = off; off += s_len[i]; }
            g_seg_node_start[BATCH] = off;
        }
    }
}

// ============ K2: slab pieces, cp.async double-buffered stream + last-arriver combine ============
extern __shared__ char dynsmem[];   // 64KB: warp rings; s_acc aliased after streaming

__global__ void __launch_bounds__(256, 2) k2_phase1(const float* __restrict__ mem,
                                                    float* __restrict__ out) {
    __shared__ float s_m[8], s_z[8];
    __shared__ int   s_segstart[BATCH + 1];
    __shared__ int   s_last;

    int t    = threadIdx.x;
    int warp = t >> 5;
    int lane = t & 31;
    int cta  = blockIdx.x;

    // shared-space base address for cp.async
    unsigned int smem_u32;
    asm("{ .reg .u64 tmp; cvta.to.shared.u64 tmp, %1; cvt.u32.u64 %0, tmp; }"
        : "=r"(smem_u32) : "l"(dynsmem));
    unsigned int ring0 = smem_u32 + warp * 2 * 4096 + lane * 16;

    for (int i = t; i <= BATCH; i += 256) s_segstart[i] = g_seg_node_start[i];
    __syncthreads();

    int row_lo = cta * SLAB;
    int row_hi = row_lo + SLAB;
    if (row_hi > NTOT) row_hi = NTOT;

    int seg = 0;
    while (s_segstart[seg + 1] <= row_lo) seg++;

    int lo = row_lo;
    while (lo < row_hi) {
        int segstart = s_segstart[seg];
        int segend   = s_segstart[seg + 1];
        int hi  = segend < row_hi ? segend : row_hi;
        int cnt = hi - lo;

        // v row for this segment (L2-hot), register-resident
        const float4* vp = (const float4*)(g_v + seg * DIM);
        float4 v[8];
#pragma unroll
        for (int j = 0; j < 8; j++) v[j] = vp[j * 32 + lane];

        float m = -INFINITY, z = 0.f;
        float4 acc[8];
#pragma unroll
        for (int j = 0; j < 8; j++) acc[j] = make_float4(0.f, 0.f, 0.f, 0.f);

        // ---- cp.async double-buffered row stream (warp-private ring) ----
        if (warp < cnt) {   // preload first row into buf 0
            const char* src = (const char*)(mem + (size_t)(lo + warp) * DIM) + lane * 16;
#pragma unroll
            for (int j = 0; j < 8; j++) CP_ASYNC16(ring0 + j * 512, src + j * 512);
            CP_COMMIT();
        }

        int d = 0;
        for (int i = warp; i < cnt; i += 8) {
            int nxt = i + 8;
            if (nxt < cnt) {   // issue next row into alternate buffer
                unsigned int dst = ring0 + (1 - d) * 4096;
                const char* src = (const char*)(mem + (size_t)(lo + nxt) * DIM) + lane * 16;
#pragma unroll
                for (int j = 0; j < 8; j++) CP_ASYNC16(dst + j * 512, src + j * 512);
                CP_COMMIT();
                CP_WAIT1();    // current buffer complete, next in flight
            } else {
                CP_WAIT0();
            }

            // read current buffer (lane reads only its own copied bytes)
            const char* buf = dynsmem + warp * 2 * 4096 + d * 4096 + lane * 16;
            float4 r[8];
#pragma unroll
            for (int j = 0; j < 8; j++) r[j] = *(const float4*)(buf + j * 512);

            float s0 = 0.f, s1 = 0.f;
#pragma unroll
            for (int j = 0; j < 8; j += 2) {
                s0 += r[j].x * v[j].x + r[j].y * v[j].y + r[j].z * v[j].z + r[j].w * v[j].w;
                s1 += r[j+1].x * v[j+1].x + r[j+1].y * v[j+1].y + r[j+1].z * v[j+1].z + r[j+1].w * v[j+1].w;
            }
            float s = s0 + s1;
#pragma unroll
            for (int o = 16; o > 0; o >>= 1) s += __shfl_xor_sync(0xffffffffu, s, o);

            if (s > m) {
                float sc = __expf(m - s);   // exp(-inf)=0 handles first row
                z = z * sc + 1.f;
#pragma unroll
                for (int j = 0; j < 8; j++) {
                    acc[j].x = acc[j].x * sc + r[j].x;
                    acc[j].y = acc[j].y * sc + r[j].y;
                    acc[j].z = acc[j].z * sc + r[j].z;
                    acc[j].w = acc[j].w * sc + r[j].w;
                }
                m = s;
            } else {
                float w8 = __expf(s - m);
                z += w8;
#pragma unroll
                for (int j = 0; j < 8; j++) {
                    acc[j].x = fmaf(w8, r[j].x, acc[j].x);
                    acc[j].y = fmaf(w8, r[j].y, acc[j].y);
                    acc[j].z = fmaf(w8, r[j].z, acc[j].z);
                    acc[j].w = fmaf(w8, r[j].w, acc[j].w);
                }
            }
            d ^= 1;
        }

        // ---- combine 8 warp accumulators (s_acc aliased over the ring) ----
        __syncthreads();   // all warps' cp.async complete; ring reusable as s_acc
        float4 (*s_acc)[256] = (float4 (*)[256])dynsmem;
#pragma unroll
        for (int j = 0; j < 8; j++) s_acc[warp][j * 32 + lane] = acc[j];
        if (lane == 0) { s_m[warp] = m; s_z[warp] = z; }
        __syncthreads();

        float m_b = -INFINITY;
#pragma unroll
        for (int w = 0; w < 8; w++) m_b = fmaxf(m_b, s_m[w]);

        float  z_b = 0.f;
        float4 a   = make_float4(0.f, 0.f, 0.f, 0.f);
#pragma unroll
        for (int w = 0; w < 8; w++) {
            float mw = s_m[w];
            float sc = (mw == -INFINITY) ? 0.f : __expf(mw - m_b);  // idle warp -> 0
            float4 aw = s_acc[w][t];
            a.x = fmaf(sc, aw.x, a.x);
            a.y = fmaf(sc, aw.y, a.y);
            a.z = fmaf(sc, aw.z, a.z);
            a.w = fmaf(sc, aw.w, a.w);
            z_b = fmaf(sc, s_z[w], z_b);
        }

        // deterministic partial slot: slab index relative to segment's first slab
        int first_slab = segstart / SLAB;
        int slot = cta - first_slab;
        int base = seg * SLOTS + slot;
        g_part_acc[(size_t)base * (DIM / 4) + t] = a;
        if (t == 0) { g_part_m[base] = m_b; g_part_z[base] = z_b; }

        // ---- event-driven last-arriver: final combine for this segment ----
        __threadfence();
        __syncthreads();
        int np = (segend - 1) / SLAB - first_slab + 1;
        if (t == 0)
            s_last = (atomicAdd(&g_seg_done[seg], 1) == np - 1) ? 1 : 0;
        __syncthreads();
        if (s_last) {
            __threadfence();   // acquire: other pieces' partials visible
            int b0s = seg * SLOTS;
            float m_g = -INFINITY;
            for (int ci = 0; ci < np; ci++) m_g = fmaxf(m_g, g_part_m[b0s + ci]);

            float  zg = 0.f;
            float4 ag = make_float4(0.f, 0.f, 0.f, 0.f);
            for (int ci = 0; ci < np; ci++) {
                float sc = __expf(g_part_m[b0s + ci] - m_g);
                float4 p = g_part_acc[(size_t)(b0s + ci) * (DIM / 4) + t];
                ag.x = fmaf(sc, p.x, ag.x);
                ag.y = fmaf(sc, p.y, ag.y);
                ag.z = fmaf(sc, p.z, ag.z);
                ag.w = fmaf(sc, p.w, ag.w);
                zg = fmaf(sc, g_part_z[b0s + ci], zg);
            }
            float inv = 1.f / zg;
            ((float4*)out)[seg * (DIM / 4) + t] =
                make_float4(ag.x * inv, ag.y * inv, ag.z * inv, ag.w * inv);
            if (t == 0) g_seg_done[seg] = 0;   // self-clean for graph replay
        }
        __syncthreads();   // protect ring/s_acc before next piece

        lo = hi;
        seg++;
    }
}

// ---------------- launch ----------------
extern "C" void kernel_launch(void* const* d_in, const int* in_sizes, int n_in,
                              void* d_out, int out_size) {
    // Identify inputs by element count (ordering-proof):
    //   memory_bank 67108864, decoder_state 65536, W 1048576, lens 64.
    const float* mem    = nullptr;
    const float* dstate = nullptr;
    const float* W      = nullptr;
    const int*   lens   = nullptr;
    for (int i = 0; i < n_in; i++) {
        switch (in_sizes[i]) {
            case 67108864: mem    = (const float*)d_in[i]; break;
            case 65536:    dstate = (const float*)d_in[i]; break;
            case 1048576:  W      = (const float*)d_in[i]; break;
            case 64:       lens   = (const int*)d_in[i];   break;
        }
    }
    float* out = (float*)d_out;

    static bool attr_set = false;
    if (!attr_set) {
        cudaFuncSetAttribute(k2_phase1, cudaFuncAttributeMaxDynamicSharedMemorySize,
                             RING_BYTES);
        attr_set = true;
    }

    k1_vproj_setup<<<dim3(4, 4, NSPLIT), 256>>>(dstate, W, lens);
    k2_phase1<<<NPIECE, 256, RING_BYTES>>>(mem, out);
}